// round 12
// baseline (speedup 1.0000x reference)
#include <cuda_runtime.h>
#include <cuda_bf16.h>

// BOWRegression: out[b] = sigmoid( sum_{distinct tok in text[:,b], tok != PAD} W[tok] + bias )
//
// text: [T=200, B=4096] token ids (int64 OR int32 -- detected at runtime)
// W:    [V=100000] float32
// b:    [1] float32
// out:  [B] float32
//
// One CTA per batch column. Tokens -> SMEM, O(T^2) dedup via broadcast LDS
// (first-occurrence wins), gather W from L2, block reduce, sigmoid.

#define T_TOK 200
#define BATCH 4096
#define PAD_TOK 1
#define NTHREADS 256

__global__ __launch_bounds__(NTHREADS, 8)
void bow_regression_kernel(const int* __restrict__ text32,
                           const float* __restrict__ W,
                           const float* __restrict__ bias,
                           float* __restrict__ out)
{
    __shared__ int toks[T_TOK];
    __shared__ float warp_sums[NTHREADS / 32];
    __shared__ int is64_sh;

    const int b   = blockIdx.x;
    const int tid = threadIdx.x;

    // ---- runtime dtype detection (int64 vs int32 token array) ----
    // If int64: tokens are (low=value, high=0) word pairs -> all odd 32-bit
    // words are 0 (values are small nonneg). If int32: odd words are random
    // token ids in [0,100000); probability all 32 checked words are zero is
    // ~(1e-5)^32 ~= 0. Deterministic for fixed inputs.
    if (tid == 0) {
        int all0 = 1;
        #pragma unroll
        for (int k = 1; k < 64; k += 2) {
            all0 &= (text32[k] == 0);
        }
        is64_sh = all0;
    }
    __syncthreads();
    const bool is64 = (is64_sh != 0);

    // ---- load this column's tokens into SMEM ----
    if (tid < T_TOK) {
        int tok;
        if (is64) {
            // low 32-bit word of int64 at logical index (tid*BATCH + b)
            tok = text32[((long long)tid * BATCH + b) * 2];
        } else {
            tok = text32[tid * BATCH + b];
        }
        toks[tid] = tok;
    }
    __syncthreads();

    // ---- dedup (keep first occurrence) + gather W ----
    float val = 0.0f;
    if (tid < T_TOK) {
        const int tok = toks[tid];
        bool keep = (tok != PAD_TOK);
        // broadcast LDS scan: all threads read the same toks[j] each
        // iteration (no bank conflicts). First occurrence wins.
        #pragma unroll 8
        for (int j = 0; j < T_TOK; j++) {
            if (j < tid && toks[j] == tok) keep = false;
        }
        if (keep) val = __ldg(&W[tok]);
    }

    // ---- block reduction ----
    #pragma unroll
    for (int o = 16; o > 0; o >>= 1)
        val += __shfl_down_sync(0xffffffffu, val, o);
    if ((tid & 31) == 0) warp_sums[tid >> 5] = val;
    __syncthreads();

    if (tid == 0) {
        float s = 0.0f;
        #pragma unroll
        for (int w = 0; w < NTHREADS / 32; w++) s += warp_sums[w];
        s += bias[0];
        out[b] = 1.0f / (1.0f + expf(-s));
    }
}

extern "C" void kernel_launch(void* const* d_in, const int* in_sizes, int n_in,
                              void* d_out, int out_size)
{
    const int*   text = (const int*)d_in[0];   // int64 or int32 -- detected in-kernel
    const float* W    = (const float*)d_in[1]; // [V]
    const float* bias = (const float*)d_in[2]; // [1]
    float*       out  = (float*)d_out;         // [B]

    bow_regression_kernel<<<BATCH, NTHREADS>>>(text, W, bias, out);
}

// round 13
// speedup vs baseline: 3.3521x; 3.3521x over previous
#include <cuda_runtime.h>
#include <cuda_bf16.h>

// BOWRegression: out[b] = sigmoid( sum_{distinct tok in text[:,b], tok != PAD} W[tok] + bias )
//
// text: [T=200, B=4096] token ids (int64 OR int32 -- detected at runtime)
// W:    [V=100000] float32,  b: [1] float32,  out: [B] float32
//
// One CTA per batch column. Dedup via a per-CTA shared-memory BITMAP
// (V bits = 12.5 KB): each thread atomicOr's its token's bit; the thread
// that flips the bit 0->1 is the unique owner and gathers W[tok].
// Replaces the previous O(T^2) ALU-bound scan (alu pipe was 76%).

#define T_TOK 200
#define BATCH 4096
#define PAD_TOK 1
#define NTHREADS 256
#define BM_WORDS 3125   // ceil(100000 / 32)

__global__ __launch_bounds__(NTHREADS, 8)
void bow_regression_kernel(const int* __restrict__ text32,
                           const float* __restrict__ W,
                           const float* __restrict__ bias,
                           float* __restrict__ out)
{
    __shared__ unsigned int bitmap[BM_WORDS];
    __shared__ float warp_sums[NTHREADS / 32];
    __shared__ int is64_sh;

    const int b   = blockIdx.x;
    const int tid = threadIdx.x;

    // ---- runtime dtype detection (int64 vs int32 token array) ----
    // int64 tokens store (low=value, high=0) -> all odd 32-bit words are 0.
    // For int32 random ids in [0,100000) the chance 32 odd words are all
    // zero is ~0. Deterministic for fixed inputs.
    if (tid == 0) {
        int all0 = 1;
        #pragma unroll
        for (int k = 1; k < 64; k += 2) all0 &= (text32[k] == 0);
        is64_sh = all0;
    }

    // ---- clear bitmap (3125 words / 256 threads = 13 stores max) ----
    #pragma unroll
    for (int i = tid; i < BM_WORDS; i += NTHREADS) bitmap[i] = 0u;
    __syncthreads();

    const bool is64 = (is64_sh != 0);

    // ---- load token, set-insert via atomicOr, gather on first insert ----
    float val = 0.0f;
    if (tid < T_TOK) {
        int tok;
        if (is64) {
            tok = text32[((long long)tid * BATCH + b) * 2]; // low word of int64
        } else {
            tok = text32[tid * BATCH + b];
        }
        const unsigned int bit = 1u << (tok & 31);
        const unsigned int old = atomicOr(&bitmap[tok >> 5], bit);
        if (((old & bit) == 0u) && (tok != PAD_TOK)) {
            val = __ldg(&W[tok]);
        }
    }

    // ---- block reduction ----
    #pragma unroll
    for (int o = 16; o > 0; o >>= 1)
        val += __shfl_down_sync(0xffffffffu, val, o);
    if ((tid & 31) == 0) warp_sums[tid >> 5] = val;
    __syncthreads();

    if (tid == 0) {
        float s = 0.0f;
        #pragma unroll
        for (int w = 0; w < NTHREADS / 32; w++) s += warp_sums[w];
        s += bias[0];
        out[b] = 1.0f / (1.0f + expf(-s));
    }
}

extern "C" void kernel_launch(void* const* d_in, const int* in_sizes, int n_in,
                              void* d_out, int out_size)
{
    const int*   text = (const int*)d_in[0];
    const float* W    = (const float*)d_in[1];
    const float* bias = (const float*)d_in[2];
    float*       out  = (float*)d_out;

    bow_regression_kernel<<<BATCH, NTHREADS>>>(text, W, bias, out);
}